// round 13
// baseline (speedup 1.0000x reference)
#include <cuda_runtime.h>
#include <cuda_bf16.h>
#include <cuda_fp16.h>
#include <math.h>
#include <stdint.h>

#define NNODES 100000
#define RREL 3
#define EEDGES 500000
#define NETOT (RREL * EEDGES)
#define HHEADS 4
#define FFEAT 64
#define INFEAT 256
#define HF 256
#define NEG_SLOPE 0.2f
#define NBLK 98               // ceil(NNODES/1024)

// ---------------- scratch ----------------
__device__ __half g_z[(long)RREL * NNODES * HF];
__device__ __nv_bfloat16 g_xh[(long)NNODES * INFEAT];
__device__ __nv_bfloat16 g_xl[(long)NNODES * INFEAT];
__device__ __nv_bfloat16 g_wth[RREL * INFEAT * HF];
__device__ __nv_bfloat16 g_wtl[RREL * INFEAT * HF];
__device__ float g_el[RREL * NNODES * HHEADS];
__device__ float g_er[RREL * NNODES * HHEADS];
__device__ int   g_cnt[NNODES];
__device__ int   g_off[NNODES + 1];
__device__ int   g_pos[NNODES];
__device__ int   g_bsum[NBLK];
__device__ int   g_eid[NETOT];    // packed (r<<19)|s

// ---------------- helpers ----------------
__device__ __forceinline__ uint32_t smem_u32(const void* p) {
    uint32_t a;
    asm("{ .reg .u64 t; cvta.to.shared.u64 t, %1; cvt.u32.u64 %0, t; }" : "=r"(a) : "l"(p));
    return a;
}
__device__ __forceinline__ void cp16(uint32_t dst, const void* src, int srcsize) {
    asm volatile("cp.async.cg.shared.global [%0], [%1], 16, %2;"
                 :: "r"(dst), "l"(src), "r"(srcsize));
}
#define CP_COMMIT() asm volatile("cp.async.commit_group;" ::: "memory")
#define CP_WAIT(n)  asm volatile("cp.async.wait_group %0;" :: "n"(n) : "memory")
#define LDMX4(r0, r1, r2, r3, addr) \
    asm volatile("ldmatrix.sync.aligned.m8n8.x4.shared.b16 {%0,%1,%2,%3}, [%4];" \
        : "=r"(r0), "=r"(r1), "=r"(r2), "=r"(r3) : "r"(addr))

__device__ __forceinline__ void mma_bf16(float* c, const uint32_t* a, const uint32_t* b) {
    asm volatile(
        "mma.sync.aligned.m16n8k16.row.col.f32.bf16.bf16.f32 "
        "{%0,%1,%2,%3}, {%4,%5,%6,%7}, {%8,%9}, {%0,%1,%2,%3};"
        : "+f"(c[0]), "+f"(c[1]), "+f"(c[2]), "+f"(c[3])
        : "r"(a[0]), "r"(a[1]), "r"(a[2]), "r"(a[3]), "r"(b[0]), "r"(b[1]));
}
__device__ __forceinline__ void split_bf16(float v, __nv_bfloat16& h, __nv_bfloat16& l) {
    h = __float2bfloat16(v);
    l = __float2bfloat16(v - __bfloat162float(h));
}

// ---------------- init ----------------
__global__ void k_zero_cnt() {
    int i = blockIdx.x * blockDim.x + threadIdx.x;
    if (i < NNODES) g_cnt[i] = 0;
}

// ---------------- precompute splits ----------------
__global__ void k_prep_x(const float* __restrict__ x) {
    long i = (long)blockIdx.x * blockDim.x + threadIdx.x;
    if (i >= (long)NNODES * INFEAT / 8) return;
    const float4* xp = (const float4*)(x + i * 8);
    float4 a = xp[0], b = xp[1];
    float v[8] = {a.x, a.y, a.z, a.w, b.x, b.y, b.z, b.w};
    __nv_bfloat16 hh[8], ll[8];
    #pragma unroll
    for (int q = 0; q < 8; q++) split_bf16(v[q], hh[q], ll[q]);
    *(uint4*)&g_xh[i * 8] = *(uint4*)hh;
    *(uint4*)&g_xl[i * 8] = *(uint4*)ll;
}

// also zeroes el/er (fused to save a serial launch)
__global__ void k_prep_w(const float* __restrict__ W) {
    int i = blockIdx.x * blockDim.x + threadIdx.x;
    if (i < RREL * INFEAT * HF) {
        int r = i / (INFEAT * HF);
        int rem = i - r * (INFEAT * HF);
        int k = rem >> 8, n = rem & 255;
        __nv_bfloat16 h, l;
        split_bf16(W[i], h, l);
        g_wth[(r * HF + n) * INFEAT + k] = h;
        g_wtl[(r * HF + n) * INFEAT + k] = l;
    }
    int stride = gridDim.x * blockDim.x;
    for (int j = i; j < RREL * NNODES * HHEADS; j += stride) {
        g_el[j] = 0.0f; g_er[j] = 0.0f;
    }
}

// ---------------- CSR build ----------------
__global__ void k_hist(const int* __restrict__ dst) {
    int e = blockIdx.x * blockDim.x + threadIdx.x;
    if (e < NETOT) atomicAdd(&g_cnt[dst[e]], 1);
}

__global__ void k_scan_a() {
    __shared__ int s[1024];
    int tid = threadIdx.x;
    int i = blockIdx.x * 1024 + tid;
    int v = (i < NNODES) ? g_cnt[i] : 0;
    s[tid] = v;
    __syncthreads();
    #pragma unroll
    for (int o = 1; o < 1024; o <<= 1) {
        int t = (tid >= o) ? s[tid - o] : 0;
        __syncthreads();
        s[tid] += t;
        __syncthreads();
    }
    if (i < NNODES) g_off[i] = s[tid] - v;
    if (tid == 1023) g_bsum[blockIdx.x] = s[1023];
}

__global__ void k_scan_b() {
    __shared__ int s[128];
    int tid = threadIdx.x;
    int v = (tid < NBLK) ? g_bsum[tid] : 0;
    s[tid] = v;
    __syncthreads();
    #pragma unroll
    for (int o = 1; o < 128; o <<= 1) {
        int t = (tid >= o) ? s[tid - o] : 0;
        __syncthreads();
        s[tid] += t;
        __syncthreads();
    }
    if (tid < NBLK) g_bsum[tid] = s[tid] - v;
}

__global__ void k_scan_c() {
    int i = blockIdx.x * blockDim.x + threadIdx.x;
    if (i < NNODES) {
        int o = g_off[i] + g_bsum[i >> 10];
        g_off[i] = o;
        g_pos[i] = o;
    }
    if (i == 0) g_off[NNODES] = NETOT;
}

__global__ void k_scatter(const int* __restrict__ src, const int* __restrict__ dst) {
    int e = blockIdx.x * blockDim.x + threadIdx.x;
    if (e >= NETOT) return;
    int r = (e >= 2 * EEDGES) ? 2 : (e >= EEDGES ? 1 : 0);
    int pos = atomicAdd(&g_pos[dst[e]], 1);
    g_eid[pos] = (r << 19) | src[e];
}

// ---------------- pipelined tensor-core GEMM + fused el/er ----------------
#define GBM 128
#define GBN 128
#define GBK 32
#define NSTEP (INFEAT / GBK)
#define ROWELEM 40
#define TILEB (128 * ROWELEM * 2)
#define STAGEB (4 * TILEB)
#define SMEMB (2 * STAGEB)

__global__ void __launch_bounds__(256, 2)
k_gemm(const float* __restrict__ attn_l, const float* __restrict__ attn_r) {
    extern __shared__ char smem[];
    const uint32_t sb = smem_u32(smem);
    const int tid  = threadIdx.x;
    const int wid  = tid >> 5;
    const int lane = tid & 31;
    const int g    = lane >> 2;
    const int t    = lane & 3;
    const int bm   = blockIdx.x * GBM;
    const int bn   = blockIdx.y * GBN;
    const int r    = blockIdx.z;

    const int mband = (wid & 1) * 64;
    const int nband = (wid >> 1) * 32;

    const int arow_lane = ((lane >> 3) & 1) * 8 + (lane & 7);
    const int ak_lane   = (lane >> 4) * 8;
    const int bn_lane   = (lane >> 4) * 8 + (lane & 7);
    const int bk_lane   = ((lane >> 3) & 1) * 8;

    float acc[4][4][4];
    #pragma unroll
    for (int mi = 0; mi < 4; mi++)
        #pragma unroll
        for (int ni = 0; ni < 4; ni++)
            #pragma unroll
            for (int q = 0; q < 4; q++) acc[mi][ni][q] = 0.f;

    auto load_stage = [&](int buf, int k0) {
        #pragma unroll
        for (int q = 0; q < 8; q++) {
            const int c   = tid + q * 256;
            const int mat = c >> 9;
            const int row = (c >> 2) & 127;
            const int seg = c & 3;
            const uint32_t dst = sb + buf * STAGEB + mat * TILEB + row * 80 + seg * 16;
            const __nv_bfloat16* src;
            int size = 16;
            if (mat < 2) {
                int gr = bm + row;
                if (gr >= NNODES) { gr = 0; size = 0; }
                src = (mat == 0 ? g_xh : g_xl) + (long)gr * INFEAT + k0 + seg * 8;
            } else {
                src = (mat == 2 ? g_wth : g_wtl) + ((long)r * HF + bn + row) * INFEAT + k0 + seg * 8;
            }
            cp16(dst, src, size);
        }
    };

    load_stage(0, 0);
    CP_COMMIT();

    for (int step = 0; step < NSTEP; step++) {
        const int buf = step & 1;
        if (step + 1 < NSTEP) {
            load_stage(buf ^ 1, (step + 1) * GBK);
            CP_COMMIT();
            CP_WAIT(1);
        } else {
            CP_WAIT(0);
        }
        __syncthreads();

        const uint32_t baseAh = sb + buf * STAGEB;
        const uint32_t baseAl = baseAh + TILEB;
        const uint32_t baseBh = baseAh + 2 * TILEB;
        const uint32_t baseBl = baseAh + 3 * TILEB;

        #pragma unroll
        for (int kf = 0; kf < 2; kf++) {
            const int kk = kf * 16;
            uint32_t bh[4][2], bl[4][2];
            #pragma unroll
            for (int np = 0; np < 2; np++) {
                const uint32_t off =
                    ((nband + np * 16 + bn_lane) * ROWELEM + kk + bk_lane) * 2;
                LDMX4(bh[np * 2][0], bh[np * 2][1], bh[np * 2 + 1][0], bh[np * 2 + 1][1],
                      baseBh + off);
                LDMX4(bl[np * 2][0], bl[np * 2][1], bl[np * 2 + 1][0], bl[np * 2 + 1][1],
                      baseBl + off);
            }
            #pragma unroll
            for (int mi = 0; mi < 4; mi++) {
                const uint32_t offA =
                    ((mband + mi * 16 + arow_lane) * ROWELEM + kk + ak_lane) * 2;
                uint32_t ah[4], al[4];
                LDMX4(ah[0], ah[1], ah[2], ah[3], baseAh + offA);
                LDMX4(al[0], al[1], al[2], al[3], baseAl + offA);
                #pragma unroll
                for (int ni = 0; ni < 4; ni++) {
                    mma_bf16(acc[mi][ni], ah, bh[ni]);
                    mma_bf16(acc[mi][ni], ah, bl[ni]);
                    mma_bf16(acc[mi][ni], al, bh[ni]);
                }
            }
        }
        __syncthreads();
    }

    const int head = (bn + nband) >> 6;
    float alc[4][2], arc[4][2];
    #pragma unroll
    for (int ni = 0; ni < 4; ni++)
        #pragma unroll
        for (int j = 0; j < 2; j++) {
            const int col = bn + nband + ni * 8 + t * 2 + j;
            alc[ni][j] = attn_l[r * HF + col];
            arc[ni][j] = attn_r[r * HF + col];
        }

    #pragma unroll
    for (int mi = 0; mi < 4; mi++) {
        #pragma unroll
        for (int rh = 0; rh < 2; rh++) {
            const int row = mband + mi * 16 + g + rh * 8;
            const int gr  = bm + row;
            const bool ok = (gr < NNODES);
            float sl = 0.f, sr = 0.f;
            #pragma unroll
            for (int ni = 0; ni < 4; ni++) {
                const float z0 = acc[mi][ni][rh * 2 + 0];
                const float z1 = acc[mi][ni][rh * 2 + 1];
                sl = fmaf(z0, alc[ni][0], sl); sl = fmaf(z1, alc[ni][1], sl);
                sr = fmaf(z0, arc[ni][0], sr); sr = fmaf(z1, arc[ni][1], sr);
                if (ok) {
                    const int col = bn + nband + ni * 8 + t * 2;
                    __half2 zz = __floats2half2_rn(z0, z1);
                    *(__half2*)&g_z[((long)r * NNODES + gr) * HF + col] = zz;
                }
            }
            sl += __shfl_xor_sync(0xffffffffu, sl, 1);
            sl += __shfl_xor_sync(0xffffffffu, sl, 2);
            sr += __shfl_xor_sync(0xffffffffu, sr, 1);
            sr += __shfl_xor_sync(0xffffffffu, sr, 2);
            if (ok && t == 0) {
                atomicAdd(&g_el[((long)r * NNODES + gr) * HHEADS + head], sl);
                atomicAdd(&g_er[((long)r * NNODES + gr) * HHEADS + head], sr);
            }
        }
    }
}

// ---------------- single-pass pull aggregation + bias + ELU ----------------
// 64 threads per dst; the 16 lanes of one head share el/exp via shuffle.
__global__ void k_agg(const float* __restrict__ bias, float* __restrict__ out) {
    int tid = threadIdx.x;
    int d = blockIdx.x * 4 + (tid >> 6);
    int g = tid & 63;
    if (d >= NNODES) return;      // whole warps exit together (warp ⊂ group)
    int h = g >> 4;
    int lane = tid & 31;

    int off0 = g_off[d];
    int off1 = g_off[d + 1];

    float er0 = g_er[((long)0 * NNODES + d) * HHEADS + h];
    float er1 = g_er[((long)1 * NNODES + d) * HHEADS + h];
    float er2 = g_er[((long)2 * NNODES + d) * HHEADS + h];

    float n0x = 0.f, n0y = 0.f, n0z = 0.f, n0w = 0.f, den0 = 0.f;
    float n1x = 0.f, n1y = 0.f, n1z = 0.f, n1w = 0.f, den1 = 0.f;
    float n2x = 0.f, n2y = 0.f, n2z = 0.f, n2w = 0.f, den2 = 0.f;

    const bool leader = (lane & 15) == 0;

    #pragma unroll 4
    for (int i = off0; i < off1; i++) {
        int p = __ldg(&g_eid[i]);
        int r = p >> 19;
        int s = p & 0x7FFFF;
        long idx = (long)r * NNODES + s;

        float evp = 0.f;
        if (leader) {
            float erv = (r == 0) ? er0 : (r == 1) ? er1 : er2;
            float v = __ldg(&g_el[idx * HHEADS + h]) + erv;
            v = (v > 0.f) ? v : NEG_SLOPE * v;
            evp = expf(v);
        }
        float ev = __shfl_sync(0xffffffffu, evp, lane & 16);

        uint2 zr = *(const uint2*)&g_z[idx * HF + g * 4];
        float2 f0 = __half22float2(*(const __half2*)&zr.x);
        float2 f1 = __half22float2(*(const __half2*)&zr.y);
        if (r == 0) {
            den0 += ev;
            n0x = fmaf(ev, f0.x, n0x); n0y = fmaf(ev, f0.y, n0y);
            n0z = fmaf(ev, f1.x, n0z); n0w = fmaf(ev, f1.y, n0w);
        } else if (r == 1) {
            den1 += ev;
            n1x = fmaf(ev, f0.x, n1x); n1y = fmaf(ev, f0.y, n1y);
            n1z = fmaf(ev, f1.x, n1z); n1w = fmaf(ev, f1.y, n1w);
        } else {
            den2 += ev;
            n2x = fmaf(ev, f0.x, n2x); n2y = fmaf(ev, f0.y, n2y);
            n2z = fmaf(ev, f1.x, n2z); n2w = fmaf(ev, f1.y, n2w);
        }
    }

    float i0 = (den0 != 0.f) ? 1.0f / den0 : 0.f;
    float i1 = (den1 != 0.f) ? 1.0f / den1 : 0.f;
    float i2 = (den2 != 0.f) ? 1.0f / den2 : 0.f;

    float a0 = n0x * i0 + n1x * i1 + n2x * i2;
    float a1 = n0y * i0 + n1y * i1 + n2y * i2;
    float a2 = n0z * i0 + n1z * i1 + n2z * i2;
    float a3 = n0w * i0 + n1w * i1 + n2w * i2;

    int c = g * 4;
    float b0 = bias[c + 0] + bias[HF + c + 0] + bias[2 * HF + c + 0];
    float b1 = bias[c + 1] + bias[HF + c + 1] + bias[2 * HF + c + 1];
    float b2 = bias[c + 2] + bias[HF + c + 2] + bias[2 * HF + c + 2];
    float b3 = bias[c + 3] + bias[HF + c + 3] + bias[2 * HF + c + 3];
    float v0 = a0 + b0, v1 = a1 + b1, v2 = a2 + b2, v3 = a3 + b3;
    v0 = (v0 > 0.f) ? v0 : expm1f(v0);
    v1 = (v1 > 0.f) ? v1 : expm1f(v1);
    v2 = (v2 > 0.f) ? v2 : expm1f(v2);
    v3 = (v3 > 0.f) ? v3 : expm1f(v3);
    *(float4*)&out[(long)d * HF + c] = make_float4(v0, v1, v2, v3);
}

// ---------------- launch (CSR build overlapped on a second stream) ---------
static cudaStream_t g_s1 = 0;
static cudaEvent_t g_evFork = 0, g_evJoin = 0;

extern "C" void kernel_launch(void* const* d_in, const int* in_sizes, int n_in,
                              void* d_out, int out_size) {
    const float* x      = (const float*)d_in[0];
    const float* W      = (const float*)d_in[1];
    const float* attn_l = (const float*)d_in[2];
    const float* attn_r = (const float*)d_in[3];
    const float* bias   = (const float*)d_in[4];
    const int*   src    = (const int*)d_in[5];
    const int*   dst    = (const int*)d_in[6];
    float* out = (float*)d_out;

    if (g_s1 == 0) {
        cudaStreamCreateWithFlags(&g_s1, cudaStreamNonBlocking);
        cudaEventCreateWithFlags(&g_evFork, cudaEventDisableTiming);
        cudaEventCreateWithFlags(&g_evJoin, cudaEventDisableTiming);
        cudaFuncSetAttribute(k_gemm, cudaFuncAttributeMaxDynamicSharedMemorySize, SMEMB);
    }

    // fork: CSR build on side stream
    cudaEventRecord(g_evFork, 0);
    cudaStreamWaitEvent(g_s1, g_evFork, 0);
    k_zero_cnt<<<(NNODES + 255) / 256, 256, 0, g_s1>>>();
    k_hist<<<(NETOT + 255) / 256, 256, 0, g_s1>>>(dst);
    k_scan_a<<<NBLK, 1024, 0, g_s1>>>();
    k_scan_b<<<1, 128, 0, g_s1>>>();
    k_scan_c<<<(NNODES + 255) / 256, 256, 0, g_s1>>>();
    k_scatter<<<(NETOT + 255) / 256, 256, 0, g_s1>>>(src, dst);
    cudaEventRecord(g_evJoin, g_s1);

    // main stream: prep + GEMM
    k_prep_x<<<(int)(((long)NNODES * INFEAT / 8 + 255) / 256), 256>>>(x);
    k_prep_w<<<(RREL * INFEAT * HF + 255) / 256, 256>>>(W);

    dim3 gg((NNODES + GBM - 1) / GBM, HF / GBN, RREL);
    k_gemm<<<gg, 256, SMEMB>>>(attn_l, attn_r);

    // join: aggregation needs both CSR and z/el/er
    cudaStreamWaitEvent(0, g_evJoin, 0);
    k_agg<<<(NNODES + 3) / 4, 256>>>(bias, out);
}

// round 14
// speedup vs baseline: 1.1763x; 1.1763x over previous
#include <cuda_runtime.h>
#include <cuda_bf16.h>
#include <cuda_fp16.h>
#include <math.h>
#include <stdint.h>

#define NNODES 100000
#define RREL 3
#define EEDGES 500000
#define NETOT (RREL * EEDGES)
#define HHEADS 4
#define FFEAT 64
#define INFEAT 256
#define HF 256
#define NEG_SLOPE 0.2f
#define NBLK 98               // ceil(NNODES/1024)

// ---------------- scratch ----------------
__device__ __half g_z[(long)RREL * NNODES * HF];
__device__ __nv_bfloat16 g_xh[(long)NNODES * INFEAT];
__device__ __nv_bfloat16 g_xl[(long)NNODES * INFEAT];
__device__ __nv_bfloat16 g_wth[RREL * INFEAT * HF];
__device__ __nv_bfloat16 g_wtl[RREL * INFEAT * HF];
__device__ float g_el[RREL * NNODES * HHEADS];
__device__ float g_er[RREL * NNODES * HHEADS];
__device__ int   g_cnt[NNODES];
__device__ int   g_off[NNODES + 1];
__device__ int   g_pos[NNODES];
__device__ int   g_bsum[NBLK];
__device__ int   g_eid[NETOT];    // packed (r<<19)|s

// ---------------- helpers ----------------
__device__ __forceinline__ uint32_t smem_u32(const void* p) {
    uint32_t a;
    asm("{ .reg .u64 t; cvta.to.shared.u64 t, %1; cvt.u32.u64 %0, t; }" : "=r"(a) : "l"(p));
    return a;
}
__device__ __forceinline__ void cp16(uint32_t dst, const void* src, int srcsize) {
    asm volatile("cp.async.cg.shared.global [%0], [%1], 16, %2;"
                 :: "r"(dst), "l"(src), "r"(srcsize));
}
#define CP_COMMIT() asm volatile("cp.async.commit_group;" ::: "memory")
#define CP_WAIT(n)  asm volatile("cp.async.wait_group %0;" :: "n"(n) : "memory")
#define LDMX4(r0, r1, r2, r3, addr) \
    asm volatile("ldmatrix.sync.aligned.m8n8.x4.shared.b16 {%0,%1,%2,%3}, [%4];" \
        : "=r"(r0), "=r"(r1), "=r"(r2), "=r"(r3) : "r"(addr))

__device__ __forceinline__ void mma_bf16(float* c, const uint32_t* a, const uint32_t* b) {
    asm volatile(
        "mma.sync.aligned.m16n8k16.row.col.f32.bf16.bf16.f32 "
        "{%0,%1,%2,%3}, {%4,%5,%6,%7}, {%8,%9}, {%0,%1,%2,%3};"
        : "+f"(c[0]), "+f"(c[1]), "+f"(c[2]), "+f"(c[3])
        : "r"(a[0]), "r"(a[1]), "r"(a[2]), "r"(a[3]), "r"(b[0]), "r"(b[1]));
}
__device__ __forceinline__ void split_bf16(float v, __nv_bfloat16& h, __nv_bfloat16& l) {
    h = __float2bfloat16(v);
    l = __float2bfloat16(v - __bfloat162float(h));
}

// ---------------- init ----------------
__global__ void k_zero_elr() {
    int i = blockIdx.x * blockDim.x + threadIdx.x;
    int stride = gridDim.x * blockDim.x;
    for (int j = i; j < RREL * NNODES * HHEADS; j += stride) {
        g_el[j] = 0.0f; g_er[j] = 0.0f;
    }
}
__global__ void k_zero_cnt() {
    int i = blockIdx.x * blockDim.x + threadIdx.x;
    if (i < NNODES) g_cnt[i] = 0;
}

// ---------------- precompute splits ----------------
__global__ void k_prep_x(const float* __restrict__ x) {
    long i = (long)blockIdx.x * blockDim.x + threadIdx.x;
    if (i >= (long)NNODES * INFEAT / 8) return;
    const float4* xp = (const float4*)(x + i * 8);
    float4 a = xp[0], b = xp[1];
    float v[8] = {a.x, a.y, a.z, a.w, b.x, b.y, b.z, b.w};
    __nv_bfloat16 hh[8], ll[8];
    #pragma unroll
    for (int q = 0; q < 8; q++) split_bf16(v[q], hh[q], ll[q]);
    *(uint4*)&g_xh[i * 8] = *(uint4*)hh;
    *(uint4*)&g_xl[i * 8] = *(uint4*)ll;
}

__global__ void k_prep_w(const float* __restrict__ W) {
    int i = blockIdx.x * blockDim.x + threadIdx.x;
    if (i >= RREL * INFEAT * HF) return;
    int r = i / (INFEAT * HF);
    int rem = i - r * (INFEAT * HF);
    int k = rem >> 8, n = rem & 255;
    __nv_bfloat16 h, l;
    split_bf16(W[i], h, l);
    g_wth[(r * HF + n) * INFEAT + k] = h;
    g_wtl[(r * HF + n) * INFEAT + k] = l;
}

// ---------------- CSR build ----------------
__global__ void k_hist(const int* __restrict__ dst) {
    int e = blockIdx.x * blockDim.x + threadIdx.x;
    if (e < NETOT) atomicAdd(&g_cnt[dst[e]], 1);
}

__global__ void k_scan_a() {
    __shared__ int s[1024];
    int tid = threadIdx.x;
    int i = blockIdx.x * 1024 + tid;
    int v = (i < NNODES) ? g_cnt[i] : 0;
    s[tid] = v;
    __syncthreads();
    #pragma unroll
    for (int o = 1; o < 1024; o <<= 1) {
        int t = (tid >= o) ? s[tid - o] : 0;
        __syncthreads();
        s[tid] += t;
        __syncthreads();
    }
    if (i < NNODES) g_off[i] = s[tid] - v;
    if (tid == 1023) g_bsum[blockIdx.x] = s[1023];
}

__global__ void k_scan_b() {
    __shared__ int s[128];
    int tid = threadIdx.x;
    int v = (tid < NBLK) ? g_bsum[tid] : 0;
    s[tid] = v;
    __syncthreads();
    #pragma unroll
    for (int o = 1; o < 128; o <<= 1) {
        int t = (tid >= o) ? s[tid - o] : 0;
        __syncthreads();
        s[tid] += t;
        __syncthreads();
    }
    if (tid < NBLK) g_bsum[tid] = s[tid] - v;
}

__global__ void k_scan_c() {
    int i = blockIdx.x * blockDim.x + threadIdx.x;
    if (i < NNODES) {
        int o = g_off[i] + g_bsum[i >> 10];
        g_off[i] = o;
        g_pos[i] = o;
    }
    if (i == 0) g_off[NNODES] = NETOT;
}

__global__ void k_scatter(const int* __restrict__ src, const int* __restrict__ dst) {
    int e = blockIdx.x * blockDim.x + threadIdx.x;
    if (e >= NETOT) return;
    int r = (e >= 2 * EEDGES) ? 2 : (e >= EEDGES ? 1 : 0);
    int pos = atomicAdd(&g_pos[dst[e]], 1);
    g_eid[pos] = (r << 19) | src[e];
}

// ---------------- pipelined tensor-core GEMM + fused el/er ----------------
#define GBM 128
#define GBN 128
#define GBK 32
#define NSTEP (INFEAT / GBK)
#define ROWELEM 40
#define TILEB (128 * ROWELEM * 2)
#define STAGEB (4 * TILEB)
#define SMEMB (2 * STAGEB)

__global__ void __launch_bounds__(256, 2)
k_gemm(const float* __restrict__ attn_l, const float* __restrict__ attn_r) {
    extern __shared__ char smem[];
    const uint32_t sb = smem_u32(smem);
    const int tid  = threadIdx.x;
    const int wid  = tid >> 5;
    const int lane = tid & 31;
    const int g    = lane >> 2;
    const int t    = lane & 3;
    const int bm   = blockIdx.x * GBM;
    const int bn   = blockIdx.y * GBN;
    const int r    = blockIdx.z;

    const int mband = (wid & 1) * 64;
    const int nband = (wid >> 1) * 32;

    const int arow_lane = ((lane >> 3) & 1) * 8 + (lane & 7);
    const int ak_lane   = (lane >> 4) * 8;
    const int bn_lane   = (lane >> 4) * 8 + (lane & 7);
    const int bk_lane   = ((lane >> 3) & 1) * 8;

    float acc[4][4][4];
    #pragma unroll
    for (int mi = 0; mi < 4; mi++)
        #pragma unroll
        for (int ni = 0; ni < 4; ni++)
            #pragma unroll
            for (int q = 0; q < 4; q++) acc[mi][ni][q] = 0.f;

    auto load_stage = [&](int buf, int k0) {
        #pragma unroll
        for (int q = 0; q < 8; q++) {
            const int c   = tid + q * 256;
            const int mat = c >> 9;
            const int row = (c >> 2) & 127;
            const int seg = c & 3;
            const uint32_t dst = sb + buf * STAGEB + mat * TILEB + row * 80 + seg * 16;
            const __nv_bfloat16* src;
            int size = 16;
            if (mat < 2) {
                int gr = bm + row;
                if (gr >= NNODES) { gr = 0; size = 0; }
                src = (mat == 0 ? g_xh : g_xl) + (long)gr * INFEAT + k0 + seg * 8;
            } else {
                src = (mat == 2 ? g_wth : g_wtl) + ((long)r * HF + bn + row) * INFEAT + k0 + seg * 8;
            }
            cp16(dst, src, size);
        }
    };

    load_stage(0, 0);
    CP_COMMIT();

    for (int step = 0; step < NSTEP; step++) {
        const int buf = step & 1;
        if (step + 1 < NSTEP) {
            load_stage(buf ^ 1, (step + 1) * GBK);
            CP_COMMIT();
            CP_WAIT(1);
        } else {
            CP_WAIT(0);
        }
        __syncthreads();

        const uint32_t baseAh = sb + buf * STAGEB;
        const uint32_t baseAl = baseAh + TILEB;
        const uint32_t baseBh = baseAh + 2 * TILEB;
        const uint32_t baseBl = baseAh + 3 * TILEB;

        #pragma unroll
        for (int kf = 0; kf < 2; kf++) {
            const int kk = kf * 16;
            uint32_t bh[4][2], bl[4][2];
            #pragma unroll
            for (int np = 0; np < 2; np++) {
                const uint32_t off =
                    ((nband + np * 16 + bn_lane) * ROWELEM + kk + bk_lane) * 2;
                LDMX4(bh[np * 2][0], bh[np * 2][1], bh[np * 2 + 1][0], bh[np * 2 + 1][1],
                      baseBh + off);
                LDMX4(bl[np * 2][0], bl[np * 2][1], bl[np * 2 + 1][0], bl[np * 2 + 1][1],
                      baseBl + off);
            }
            #pragma unroll
            for (int mi = 0; mi < 4; mi++) {
                const uint32_t offA =
                    ((mband + mi * 16 + arow_lane) * ROWELEM + kk + ak_lane) * 2;
                uint32_t ah[4], al[4];
                LDMX4(ah[0], ah[1], ah[2], ah[3], baseAh + offA);
                LDMX4(al[0], al[1], al[2], al[3], baseAl + offA);
                #pragma unroll
                for (int ni = 0; ni < 4; ni++) {
                    mma_bf16(acc[mi][ni], ah, bh[ni]);
                    mma_bf16(acc[mi][ni], ah, bl[ni]);
                    mma_bf16(acc[mi][ni], al, bh[ni]);
                }
            }
        }
        __syncthreads();
    }

    const int head = (bn + nband) >> 6;
    float alc[4][2], arc[4][2];
    #pragma unroll
    for (int ni = 0; ni < 4; ni++)
        #pragma unroll
        for (int j = 0; j < 2; j++) {
            const int col = bn + nband + ni * 8 + t * 2 + j;
            alc[ni][j] = attn_l[r * HF + col];
            arc[ni][j] = attn_r[r * HF + col];
        }

    #pragma unroll
    for (int mi = 0; mi < 4; mi++) {
        #pragma unroll
        for (int rh = 0; rh < 2; rh++) {
            const int row = mband + mi * 16 + g + rh * 8;
            const int gr  = bm + row;
            const bool ok = (gr < NNODES);
            float sl = 0.f, sr = 0.f;
            #pragma unroll
            for (int ni = 0; ni < 4; ni++) {
                const float z0 = acc[mi][ni][rh * 2 + 0];
                const float z1 = acc[mi][ni][rh * 2 + 1];
                sl = fmaf(z0, alc[ni][0], sl); sl = fmaf(z1, alc[ni][1], sl);
                sr = fmaf(z0, arc[ni][0], sr); sr = fmaf(z1, arc[ni][1], sr);
                if (ok) {
                    const int col = bn + nband + ni * 8 + t * 2;
                    __half2 zz = __floats2half2_rn(z0, z1);
                    *(__half2*)&g_z[((long)r * NNODES + gr) * HF + col] = zz;
                }
            }
            sl += __shfl_xor_sync(0xffffffffu, sl, 1);
            sl += __shfl_xor_sync(0xffffffffu, sl, 2);
            sr += __shfl_xor_sync(0xffffffffu, sr, 1);
            sr += __shfl_xor_sync(0xffffffffu, sr, 2);
            if (ok && t == 0) {
                atomicAdd(&g_el[((long)r * NNODES + gr) * HHEADS + head], sl);
                atomicAdd(&g_er[((long)r * NNODES + gr) * HHEADS + head], sr);
            }
        }
    }
}

// ---------------- single-pass pull aggregation + bias + ELU ----------------
// one dst node per 64-thread block: block retires on its own degree
__global__ void __launch_bounds__(64)
k_agg(const float* __restrict__ bias, float* __restrict__ out) {
    int d = blockIdx.x;
    int g = threadIdx.x;                    // columns [g*4, g*4+4)
    int h = g >> 4;

    int off0 = g_off[d];
    int off1 = g_off[d + 1];

    float er0 = g_er[((long)0 * NNODES + d) * HHEADS + h];
    float er1 = g_er[((long)1 * NNODES + d) * HHEADS + h];
    float er2 = g_er[((long)2 * NNODES + d) * HHEADS + h];

    float n0x = 0.f, n0y = 0.f, n0z = 0.f, n0w = 0.f, den0 = 0.f;
    float n1x = 0.f, n1y = 0.f, n1z = 0.f, n1w = 0.f, den1 = 0.f;
    float n2x = 0.f, n2y = 0.f, n2z = 0.f, n2w = 0.f, den2 = 0.f;

    #pragma unroll 4
    for (int i = off0; i < off1; i++) {
        int p = __ldg(&g_eid[i]);
        int r = p >> 19;
        int s = p & 0x7FFFF;
        long idx = (long)r * NNODES + s;
        float erv = (r == 0) ? er0 : (r == 1) ? er1 : er2;
        float v = __ldg(&g_el[idx * HHEADS + h]) + erv;
        v = (v > 0.f) ? v : NEG_SLOPE * v;
        float ev = expf(v);
        uint2 zr = *(const uint2*)&g_z[idx * HF + g * 4];
        float2 f0 = __half22float2(*(const __half2*)&zr.x);
        float2 f1 = __half22float2(*(const __half2*)&zr.y);
        if (r == 0) {
            den0 += ev;
            n0x = fmaf(ev, f0.x, n0x); n0y = fmaf(ev, f0.y, n0y);
            n0z = fmaf(ev, f1.x, n0z); n0w = fmaf(ev, f1.y, n0w);
        } else if (r == 1) {
            den1 += ev;
            n1x = fmaf(ev, f0.x, n1x); n1y = fmaf(ev, f0.y, n1y);
            n1z = fmaf(ev, f1.x, n1z); n1w = fmaf(ev, f1.y, n1w);
        } else {
            den2 += ev;
            n2x = fmaf(ev, f0.x, n2x); n2y = fmaf(ev, f0.y, n2y);
            n2z = fmaf(ev, f1.x, n2z); n2w = fmaf(ev, f1.y, n2w);
        }
    }

    float i0 = (den0 != 0.f) ? 1.0f / den0 : 0.f;
    float i1 = (den1 != 0.f) ? 1.0f / den1 : 0.f;
    float i2 = (den2 != 0.f) ? 1.0f / den2 : 0.f;

    float a0 = n0x * i0 + n1x * i1 + n2x * i2;
    float a1 = n0y * i0 + n1y * i1 + n2y * i2;
    float a2 = n0z * i0 + n1z * i1 + n2z * i2;
    float a3 = n0w * i0 + n1w * i1 + n2w * i2;

    int c = g * 4;
    float b0 = bias[c + 0] + bias[HF + c + 0] + bias[2 * HF + c + 0];
    float b1 = bias[c + 1] + bias[HF + c + 1] + bias[2 * HF + c + 1];
    float b2 = bias[c + 2] + bias[HF + c + 2] + bias[2 * HF + c + 2];
    float b3 = bias[c + 3] + bias[HF + c + 3] + bias[2 * HF + c + 3];
    float v0 = a0 + b0, v1 = a1 + b1, v2 = a2 + b2, v3 = a3 + b3;
    v0 = (v0 > 0.f) ? v0 : expm1f(v0);
    v1 = (v1 > 0.f) ? v1 : expm1f(v1);
    v2 = (v2 > 0.f) ? v2 : expm1f(v2);
    v3 = (v3 > 0.f) ? v3 : expm1f(v3);
    *(float4*)&out[(long)d * HF + c] = make_float4(v0, v1, v2, v3);
}

// ---------------- launch (CSR build overlapped on a second stream) ---------
static cudaStream_t g_s1 = 0;
static cudaEvent_t g_evFork = 0, g_evJoin = 0;

extern "C" void kernel_launch(void* const* d_in, const int* in_sizes, int n_in,
                              void* d_out, int out_size) {
    const float* x      = (const float*)d_in[0];
    const float* W      = (const float*)d_in[1];
    const float* attn_l = (const float*)d_in[2];
    const float* attn_r = (const float*)d_in[3];
    const float* bias   = (const float*)d_in[4];
    const int*   src    = (const int*)d_in[5];
    const int*   dst    = (const int*)d_in[6];
    float* out = (float*)d_out;

    if (g_s1 == 0) {
        cudaStreamCreateWithFlags(&g_s1, cudaStreamNonBlocking);
        cudaEventCreateWithFlags(&g_evFork, cudaEventDisableTiming);
        cudaEventCreateWithFlags(&g_evJoin, cudaEventDisableTiming);
        cudaFuncSetAttribute(k_gemm, cudaFuncAttributeMaxDynamicSharedMemorySize, SMEMB);
    }

    // fork: CSR build on side stream
    cudaEventRecord(g_evFork, 0);
    cudaStreamWaitEvent(g_s1, g_evFork, 0);
    k_zero_cnt<<<(NNODES + 255) / 256, 256, 0, g_s1>>>();
    k_hist<<<(NETOT + 255) / 256, 256, 0, g_s1>>>(dst);
    k_scan_a<<<NBLK, 1024, 0, g_s1>>>();
    k_scan_b<<<1, 128, 0, g_s1>>>();
    k_scan_c<<<(NNODES + 255) / 256, 256, 0, g_s1>>>();
    k_scatter<<<(NETOT + 255) / 256, 256, 0, g_s1>>>(src, dst);
    cudaEventRecord(g_evJoin, g_s1);

    // main stream: prep + GEMM
    k_zero_elr<<<512, 256>>>();
    k_prep_x<<<(int)(((long)NNODES * INFEAT / 8 + 255) / 256), 256>>>(x);
    k_prep_w<<<(RREL * INFEAT * HF + 255) / 256, 256>>>(W);

    dim3 gg((NNODES + GBM - 1) / GBM, HF / GBN, RREL);
    k_gemm<<<gg, 256, SMEMB>>>(attn_l, attn_r);

    // join: aggregation needs both CSR and z/el/er
    cudaStreamWaitEvent(0, g_evJoin, 0);
    k_agg<<<NNODES, 64>>>(bias, out);
}

// round 15
// speedup vs baseline: 1.3701x; 1.1647x over previous
#include <cuda_runtime.h>
#include <cuda_bf16.h>
#include <cuda_fp16.h>
#include <math.h>
#include <stdint.h>

#define NNODES 100000
#define RREL 3
#define EEDGES 500000
#define NETOT (RREL * EEDGES)
#define HHEADS 4
#define FFEAT 64
#define INFEAT 256
#define HF 256
#define NEG_SLOPE 0.2f
#define NBLK 98               // ceil(NNODES/1024)

// ---------------- scratch ----------------
__device__ __half g_z[(long)RREL * NNODES * HF];
__device__ __half g_xh[(long)NNODES * INFEAT];      // fp16(x), 51 MB
__device__ __half g_wth[RREL * INFEAT * HF];        // fp16 split of W, transposed [r][n][k]
__device__ __half g_wtl[RREL * INFEAT * HF];
__device__ float g_el[RREL * NNODES * HHEADS];
__device__ float g_er[RREL * NNODES * HHEADS];
__device__ int   g_cnt[NNODES];
__device__ int   g_off[NNODES + 1];
__device__ int   g_pos[NNODES];
__device__ int   g_bsum[NBLK];
__device__ int   g_eid[NETOT];    // packed (r<<19)|s

// ---------------- helpers ----------------
__device__ __forceinline__ uint32_t smem_u32(const void* p) {
    uint32_t a;
    asm("{ .reg .u64 t; cvta.to.shared.u64 t, %1; cvt.u32.u64 %0, t; }" : "=r"(a) : "l"(p));
    return a;
}
__device__ __forceinline__ void cp16(uint32_t dst, const void* src, int srcsize) {
    asm volatile("cp.async.cg.shared.global [%0], [%1], 16, %2;"
                 :: "r"(dst), "l"(src), "r"(srcsize));
}
#define CP_COMMIT() asm volatile("cp.async.commit_group;" ::: "memory")
#define CP_WAIT(n)  asm volatile("cp.async.wait_group %0;" :: "n"(n) : "memory")
#define LDMX4(r0, r1, r2, r3, addr) \
    asm volatile("ldmatrix.sync.aligned.m8n8.x4.shared.b16 {%0,%1,%2,%3}, [%4];" \
        : "=r"(r0), "=r"(r1), "=r"(r2), "=r"(r3) : "r"(addr))

__device__ __forceinline__ void mma_f16(float* c, const uint32_t* a, const uint32_t* b) {
    asm volatile(
        "mma.sync.aligned.m16n8k16.row.col.f32.f16.f16.f32 "
        "{%0,%1,%2,%3}, {%4,%5,%6,%7}, {%8,%9}, {%0,%1,%2,%3};"
        : "+f"(c[0]), "+f"(c[1]), "+f"(c[2]), "+f"(c[3])
        : "r"(a[0]), "r"(a[1]), "r"(a[2]), "r"(a[3]), "r"(b[0]), "r"(b[1]));
}

// ---------------- init ----------------
__global__ void k_zero_elr() {
    int i = blockIdx.x * blockDim.x + threadIdx.x;
    int stride = gridDim.x * blockDim.x;
    for (int j = i; j < RREL * NNODES * HHEADS; j += stride) {
        g_el[j] = 0.0f; g_er[j] = 0.0f;
    }
}
__global__ void k_zero_cnt() {
    int i = blockIdx.x * blockDim.x + threadIdx.x;
    if (i < NNODES) g_cnt[i] = 0;
}

// ---------------- precompute: x -> fp16 ----------------
__global__ void k_prep_x(const float* __restrict__ x) {
    long i = (long)blockIdx.x * blockDim.x + threadIdx.x;
    if (i >= (long)NNODES * INFEAT / 8) return;
    const float4* xp = (const float4*)(x + i * 8);
    float4 a = xp[0], b = xp[1];
    __half hh[8];
    hh[0] = __float2half_rn(a.x); hh[1] = __float2half_rn(a.y);
    hh[2] = __float2half_rn(a.z); hh[3] = __float2half_rn(a.w);
    hh[4] = __float2half_rn(b.x); hh[5] = __float2half_rn(b.y);
    hh[6] = __float2half_rn(b.z); hh[7] = __float2half_rn(b.w);
    *(uint4*)&g_xh[i * 8] = *(uint4*)hh;
}

// ---------------- precompute: W -> fp16 hi/lo, transposed ----------------
__global__ void k_prep_w(const float* __restrict__ W) {
    int i = blockIdx.x * blockDim.x + threadIdx.x;
    if (i >= RREL * INFEAT * HF) return;
    int r = i / (INFEAT * HF);
    int rem = i - r * (INFEAT * HF);
    int k = rem >> 8, n = rem & 255;
    float w = W[i];
    __half h = __float2half_rn(w);
    __half l = __float2half_rn(w - __half2float(h));
    g_wth[(r * HF + n) * INFEAT + k] = h;
    g_wtl[(r * HF + n) * INFEAT + k] = l;
}

// ---------------- CSR build ----------------
__global__ void k_hist(const int* __restrict__ dst) {
    int e = blockIdx.x * blockDim.x + threadIdx.x;
    if (e < NETOT) atomicAdd(&g_cnt[dst[e]], 1);
}

__global__ void k_scan_a() {
    __shared__ int s[1024];
    int tid = threadIdx.x;
    int i = blockIdx.x * 1024 + tid;
    int v = (i < NNODES) ? g_cnt[i] : 0;
    s[tid] = v;
    __syncthreads();
    #pragma unroll
    for (int o = 1; o < 1024; o <<= 1) {
        int t = (tid >= o) ? s[tid - o] : 0;
        __syncthreads();
        s[tid] += t;
        __syncthreads();
    }
    if (i < NNODES) g_off[i] = s[tid] - v;
    if (tid == 1023) g_bsum[blockIdx.x] = s[1023];
}

__global__ void k_scan_b() {
    __shared__ int s[128];
    int tid = threadIdx.x;
    int v = (tid < NBLK) ? g_bsum[tid] : 0;
    s[tid] = v;
    __syncthreads();
    #pragma unroll
    for (int o = 1; o < 128; o <<= 1) {
        int t = (tid >= o) ? s[tid - o] : 0;
        __syncthreads();
        s[tid] += t;
        __syncthreads();
    }
    if (tid < NBLK) g_bsum[tid] = s[tid] - v;
}

__global__ void k_scan_c() {
    int i = blockIdx.x * blockDim.x + threadIdx.x;
    if (i < NNODES) {
        int o = g_off[i] + g_bsum[i >> 10];
        g_off[i] = o;
        g_pos[i] = o;
    }
    if (i == 0) g_off[NNODES] = NETOT;
}

__global__ void k_scatter(const int* __restrict__ src, const int* __restrict__ dst) {
    int e = blockIdx.x * blockDim.x + threadIdx.x;
    if (e >= NETOT) return;
    int r = (e >= 2 * EEDGES) ? 2 : (e >= EEDGES ? 1 : 0);
    int pos = atomicAdd(&g_pos[dst[e]], 1);
    g_eid[pos] = (r << 19) | src[e];
}

// ---------------- pipelined tensor-core GEMM (fp16, 2-pass) + el/er -------
#define GBM 128
#define GBN 128
#define GBK 32
#define NSTEP (INFEAT / GBK)
#define ROWELEM 40
#define TILEB (128 * ROWELEM * 2)      // 10240 B
#define STAGEB (3 * TILEB)             // Ah, Bh, Bl = 30720 B
#define SMEMB (2 * STAGEB)             // 61440 B

__global__ void __launch_bounds__(256, 2)
k_gemm(const float* __restrict__ attn_l, const float* __restrict__ attn_r) {
    extern __shared__ char smem[];
    const uint32_t sb = smem_u32(smem);
    const int tid  = threadIdx.x;
    const int wid  = tid >> 5;
    const int lane = tid & 31;
    const int g    = lane >> 2;
    const int t    = lane & 3;
    const int bm   = blockIdx.x * GBM;
    const int bn   = blockIdx.y * GBN;
    const int r    = blockIdx.z;

    const int mband = (wid & 1) * 64;
    const int nband = (wid >> 1) * 32;

    const int arow_lane = ((lane >> 3) & 1) * 8 + (lane & 7);
    const int ak_lane   = (lane >> 4) * 8;
    const int bn_lane   = (lane >> 4) * 8 + (lane & 7);
    const int bk_lane   = ((lane >> 3) & 1) * 8;

    float acc[4][4][4];
    #pragma unroll
    for (int mi = 0; mi < 4; mi++)
        #pragma unroll
        for (int ni = 0; ni < 4; ni++)
            #pragma unroll
            for (int q = 0; q < 4; q++) acc[mi][ni][q] = 0.f;

    // 1536 16B-chunks per stage / 256 threads = 6 each
    auto load_stage = [&](int buf, int k0) {
        #pragma unroll
        for (int q = 0; q < 6; q++) {
            const int c   = tid + q * 256;
            const int mat = c >> 9;            // 0:Ah 1:Bh 2:Bl
            const int row = (c >> 2) & 127;
            const int seg = c & 3;
            const uint32_t dst = sb + buf * STAGEB + mat * TILEB + row * 80 + seg * 16;
            const __half* src;
            int size = 16;
            if (mat == 0) {
                int gr = bm + row;
                if (gr >= NNODES) { gr = 0; size = 0; }
                src = g_xh + (long)gr * INFEAT + k0 + seg * 8;
            } else {
                src = (mat == 1 ? g_wth : g_wtl) + ((long)r * HF + bn + row) * INFEAT + k0 + seg * 8;
            }
            cp16(dst, src, size);
        }
    };

    load_stage(0, 0);
    CP_COMMIT();

    for (int step = 0; step < NSTEP; step++) {
        const int buf = step & 1;
        if (step + 1 < NSTEP) {
            load_stage(buf ^ 1, (step + 1) * GBK);
            CP_COMMIT();
            CP_WAIT(1);
        } else {
            CP_WAIT(0);
        }
        __syncthreads();

        const uint32_t baseA  = sb + buf * STAGEB;
        const uint32_t baseBh = baseA + TILEB;
        const uint32_t baseBl = baseA + 2 * TILEB;

        #pragma unroll
        for (int kf = 0; kf < 2; kf++) {
            const int kk = kf * 16;
            uint32_t bh[4][2], bl[4][2];
            #pragma unroll
            for (int np = 0; np < 2; np++) {
                const uint32_t off =
                    ((nband + np * 16 + bn_lane) * ROWELEM + kk + bk_lane) * 2;
                LDMX4(bh[np * 2][0], bh[np * 2][1], bh[np * 2 + 1][0], bh[np * 2 + 1][1],
                      baseBh + off);
                LDMX4(bl[np * 2][0], bl[np * 2][1], bl[np * 2 + 1][0], bl[np * 2 + 1][1],
                      baseBl + off);
            }
            #pragma unroll
            for (int mi = 0; mi < 4; mi++) {
                const uint32_t offA =
                    ((mband + mi * 16 + arow_lane) * ROWELEM + kk + ak_lane) * 2;
                uint32_t ah[4];
                LDMX4(ah[0], ah[1], ah[2], ah[3], baseA + offA);
                #pragma unroll
                for (int ni = 0; ni < 4; ni++) {
                    mma_f16(acc[mi][ni], ah, bh[ni]);
                    mma_f16(acc[mi][ni], ah, bl[ni]);
                }
            }
        }
        __syncthreads();
    }

    const int head = (bn + nband) >> 6;
    float alc[4][2], arc[4][2];
    #pragma unroll
    for (int ni = 0; ni < 4; ni++)
        #pragma unroll
        for (int j = 0; j < 2; j++) {
            const int col = bn + nband + ni * 8 + t * 2 + j;
            alc[ni][j] = attn_l[r * HF + col];
            arc[ni][j] = attn_r[r * HF + col];
        }

    #pragma unroll
    for (int mi = 0; mi < 4; mi++) {
        #pragma unroll
        for (int rh = 0; rh < 2; rh++) {
            const int row = mband + mi * 16 + g + rh * 8;
            const int gr  = bm + row;
            const bool ok = (gr < NNODES);
            float sl = 0.f, sr = 0.f;
            #pragma unroll
            for (int ni = 0; ni < 4; ni++) {
                const float z0 = acc[mi][ni][rh * 2 + 0];
                const float z1 = acc[mi][ni][rh * 2 + 1];
                sl = fmaf(z0, alc[ni][0], sl); sl = fmaf(z1, alc[ni][1], sl);
                sr = fmaf(z0, arc[ni][0], sr); sr = fmaf(z1, arc[ni][1], sr);
                if (ok) {
                    const int col = bn + nband + ni * 8 + t * 2;
                    __half2 zz = __floats2half2_rn(z0, z1);
                    *(__half2*)&g_z[((long)r * NNODES + gr) * HF + col] = zz;
                }
            }
            sl += __shfl_xor_sync(0xffffffffu, sl, 1);
            sl += __shfl_xor_sync(0xffffffffu, sl, 2);
            sr += __shfl_xor_sync(0xffffffffu, sr, 1);
            sr += __shfl_xor_sync(0xffffffffu, sr, 2);
            if (ok && t == 0) {
                atomicAdd(&g_el[((long)r * NNODES + gr) * HHEADS + head], sl);
                atomicAdd(&g_er[((long)r * NNODES + gr) * HHEADS + head], sr);
            }
        }
    }
}

// ---------------- single-pass pull aggregation + bias + ELU ----------------
// one dst node per 64-thread block
__global__ void __launch_bounds__(64)
k_agg(const float* __restrict__ bias, float* __restrict__ out) {
    int d = blockIdx.x;
    int g = threadIdx.x;                    // columns [g*4, g*4+4)
    int h = g >> 4;

    int off0 = g_off[d];
    int off1 = g_off[d + 1];

    float er0 = g_er[((long)0 * NNODES + d) * HHEADS + h];
    float er1 = g_er[((long)1 * NNODES + d) * HHEADS + h];
    float er2 = g_er[((long)2 * NNODES + d) * HHEADS + h];

    float n0x = 0.f, n0y = 0.f, n0z = 0.f, n0w = 0.f, den0 = 0.f;
    float n1x = 0.f, n1y = 0.f, n1z = 0.f, n1w = 0.f, den1 = 0.f;
    float n2x = 0.f, n2y = 0.f, n2z = 0.f, n2w = 0.f, den2 = 0.f;

    #pragma unroll 4
    for (int i = off0; i < off1; i++) {
        int p = __ldg(&g_eid[i]);
        int r = p >> 19;
        int s = p & 0x7FFFF;
        long idx = (long)r * NNODES + s;
        float erv = (r == 0) ? er0 : (r == 1) ? er1 : er2;
        float v = __ldg(&g_el[idx * HHEADS + h]) + erv;
        v = (v > 0.f) ? v : NEG_SLOPE * v;
        float ev = expf(v);
        uint2 zr = *(const uint2*)&g_z[idx * HF + g * 4];
        float2 f0 = __half22float2(*(const __half2*)&zr.x);
        float2 f1 = __half22float2(*(const __half2*)&zr.y);
        if (r == 0) {
            den0 += ev;
            n0x = fmaf(ev, f0.x, n0x); n0y = fmaf(ev, f0.y, n0y);
            n0z = fmaf(ev, f1.x, n0z); n0w = fmaf(ev, f1.y, n0w);
        } else if (r == 1) {
            den1 += ev;
            n1x = fmaf(ev, f0.x, n1x); n1y = fmaf(ev, f0.y, n1y);
            n1z = fmaf(ev, f1.x, n1z); n1w = fmaf(ev, f1.y, n1w);
        } else {
            den2 += ev;
            n2x = fmaf(ev, f0.x, n2x); n2y = fmaf(ev, f0.y, n2y);
            n2z = fmaf(ev, f1.x, n2z); n2w = fmaf(ev, f1.y, n2w);
        }
    }

    float i0 = (den0 != 0.f) ? 1.0f / den0 : 0.f;
    float i1 = (den1 != 0.f) ? 1.0f / den1 : 0.f;
    float i2 = (den2 != 0.f) ? 1.0f / den2 : 0.f;

    float a0 = n0x * i0 + n1x * i1 + n2x * i2;
    float a1 = n0y * i0 + n1y * i1 + n2y * i2;
    float a2 = n0z * i0 + n1z * i1 + n2z * i2;
    float a3 = n0w * i0 + n1w * i1 + n2w * i2;

    int c = g * 4;
    float b0 = bias[c + 0] + bias[HF + c + 0] + bias[2 * HF + c + 0];
    float b1 = bias[c + 1] + bias[HF + c + 1] + bias[2 * HF + c + 1];
    float b2 = bias[c + 2] + bias[HF + c + 2] + bias[2 * HF + c + 2];
    float b3 = bias[c + 3] + bias[HF + c + 3] + bias[2 * HF + c + 3];
    float v0 = a0 + b0, v1 = a1 + b1, v2 = a2 + b2, v3 = a3 + b3;
    v0 = (v0 > 0.f) ? v0 : expm1f(v0);
    v1 = (v1 > 0.f) ? v1 : expm1f(v1);
    v2 = (v2 > 0.f) ? v2 : expm1f(v2);
    v3 = (v3 > 0.f) ? v3 : expm1f(v3);
    *(float4*)&out[(long)d * HF + c] = make_float4(v0, v1, v2, v3);
}

// ---------------- launch (CSR build overlapped on a second stream) ---------
static cudaStream_t g_s1 = 0;
static cudaEvent_t g_evFork = 0, g_evJoin = 0;

extern "C" void kernel_launch(void* const* d_in, const int* in_sizes, int n_in,
                              void* d_out, int out_size) {
    const float* x      = (const float*)d_in[0];
    const float* W      = (const float*)d_in[1];
    const float* attn_l = (const float*)d_in[2];
    const float* attn_r = (const float*)d_in[3];
    const float* bias   = (const float*)d_in[4];
    const int*   src    = (const int*)d_in[5];
    const int*   dst    = (const int*)d_in[6];
    float* out = (float*)d_out;

    if (g_s1 == 0) {
        cudaStreamCreateWithFlags(&g_s1, cudaStreamNonBlocking);
        cudaEventCreateWithFlags(&g_evFork, cudaEventDisableTiming);
        cudaEventCreateWithFlags(&g_evJoin, cudaEventDisableTiming);
        cudaFuncSetAttribute(k_gemm, cudaFuncAttributeMaxDynamicSharedMemorySize, SMEMB);
    }

    // fork: CSR build on side stream
    cudaEventRecord(g_evFork, 0);
    cudaStreamWaitEvent(g_s1, g_evFork, 0);
    k_zero_cnt<<<(NNODES + 255) / 256, 256, 0, g_s1>>>();
    k_hist<<<(NETOT + 255) / 256, 256, 0, g_s1>>>(dst);
    k_scan_a<<<NBLK, 1024, 0, g_s1>>>();
    k_scan_b<<<1, 128, 0, g_s1>>>();
    k_scan_c<<<(NNODES + 255) / 256, 256, 0, g_s1>>>();
    k_scatter<<<(NETOT + 255) / 256, 256, 0, g_s1>>>(src, dst);
    cudaEventRecord(g_evJoin, g_s1);

    // main stream: prep + GEMM
    k_zero_elr<<<512, 256>>>();
    k_prep_x<<<(int)(((long)NNODES * INFEAT / 8 + 255) / 256), 256>>>(x);
    k_prep_w<<<(RREL * INFEAT * HF + 255) / 256, 256>>>(W);

    dim3 gg((NNODES + GBM - 1) / GBM, HF / GBN, RREL);
    k_gemm<<<gg, 256, SMEMB>>>(attn_l, attn_r);

    // join: aggregation needs both CSR and z/el/er
    cudaStreamWaitEvent(0, g_evJoin, 0);
    k_agg<<<NNODES, 64>>>(bias, out);
}

// round 16
// speedup vs baseline: 1.4061x; 1.0262x over previous
#include <cuda_runtime.h>
#include <cuda_bf16.h>
#include <cuda_fp16.h>
#include <math.h>
#include <stdint.h>

#define NNODES 100000
#define RREL 3
#define EEDGES 500000
#define NETOT (RREL * EEDGES)
#define HHEADS 4
#define FFEAT 64
#define INFEAT 256
#define HF 256
#define NEG_SLOPE 0.2f
#define NBLK 98               // ceil(NNODES/1024)

// ---------------- scratch ----------------
__device__ __half g_z[(long)RREL * NNODES * HF];
__device__ __half g_xh[(long)NNODES * INFEAT];      // fp16(x)
__device__ __half g_wth[RREL * INFEAT * HF];        // fp16 split of W, transposed [r][n][k]
__device__ __half g_wtl[RREL * INFEAT * HF];
__device__ float g_el[RREL * NNODES * HHEADS];
__device__ float g_er[RREL * NNODES * HHEADS];
__device__ int   g_cnt[NNODES];
__device__ int   g_off[NNODES + 1];
__device__ int   g_pos[NNODES];
__device__ int   g_bsum[NBLK];
__device__ int   g_eid[NETOT];    // packed (r<<19)|s

// ---------------- helpers ----------------
__device__ __forceinline__ uint32_t smem_u32(const void* p) {
    uint32_t a;
    asm("{ .reg .u64 t; cvta.to.shared.u64 t, %1; cvt.u32.u64 %0, t; }" : "=r"(a) : "l"(p));
    return a;
}
__device__ __forceinline__ void cp16(uint32_t dst, const void* src, int srcsize) {
    asm volatile("cp.async.cg.shared.global [%0], [%1], 16, %2;"
                 :: "r"(dst), "l"(src), "r"(srcsize));
}
#define CP_COMMIT() asm volatile("cp.async.commit_group;" ::: "memory")
#define CP_WAIT(n)  asm volatile("cp.async.wait_group %0;" :: "n"(n) : "memory")
#define LDMX4(r0, r1, r2, r3, addr) \
    asm volatile("ldmatrix.sync.aligned.m8n8.x4.shared.b16 {%0,%1,%2,%3}, [%4];" \
        : "=r"(r0), "=r"(r1), "=r"(r2), "=r"(r3) : "r"(addr))

__device__ __forceinline__ void mma_f16(float* c, const uint32_t* a, const uint32_t* b) {
    asm volatile(
        "mma.sync.aligned.m16n8k16.row.col.f32.f16.f16.f32 "
        "{%0,%1,%2,%3}, {%4,%5,%6,%7}, {%8,%9}, {%0,%1,%2,%3};"
        : "+f"(c[0]), "+f"(c[1]), "+f"(c[2]), "+f"(c[3])
        : "r"(a[0]), "r"(a[1]), "r"(a[2]), "r"(a[3]), "r"(b[0]), "r"(b[1]));
}

// ---------------- init ----------------
__global__ void k_zero_cnt() {
    int i = blockIdx.x * blockDim.x + threadIdx.x;
    if (i < NNODES) g_cnt[i] = 0;
}

// ---------------- precompute: x -> fp16 (+ zero el/er tail) ----------------
__global__ void k_prep_x(const float* __restrict__ x) {
    long i = (long)blockIdx.x * blockDim.x + threadIdx.x;
    if (i < (long)NNODES * INFEAT / 8) {
        const float4* xp = (const float4*)(x + i * 8);
        float4 a = xp[0], b = xp[1];
        __half hh[8];
        hh[0] = __float2half_rn(a.x); hh[1] = __float2half_rn(a.y);
        hh[2] = __float2half_rn(a.z); hh[3] = __float2half_rn(a.w);
        hh[4] = __float2half_rn(b.x); hh[5] = __float2half_rn(b.y);
        hh[6] = __float2half_rn(b.z); hh[7] = __float2half_rn(b.w);
        *(uint4*)&g_xh[i * 8] = *(uint4*)hh;
    }
    long stride = (long)gridDim.x * blockDim.x;
    for (long j = i; j < RREL * NNODES * HHEADS; j += stride) {
        g_el[j] = 0.0f; g_er[j] = 0.0f;
    }
}

// ---------------- precompute: W -> fp16 hi/lo, transposed ----------------
__global__ void k_prep_w(const float* __restrict__ W) {
    int i = blockIdx.x * blockDim.x + threadIdx.x;
    if (i >= RREL * INFEAT * HF) return;
    int r = i / (INFEAT * HF);
    int rem = i - r * (INFEAT * HF);
    int k = rem >> 8, n = rem & 255;
    float w = W[i];
    __half h = __float2half_rn(w);
    __half l = __float2half_rn(w - __half2float(h));
    g_wth[(r * HF + n) * INFEAT + k] = h;
    g_wtl[(r * HF + n) * INFEAT + k] = l;
}

// ---------------- CSR build ----------------
__global__ void k_hist(const int* __restrict__ dst) {
    int e = blockIdx.x * blockDim.x + threadIdx.x;
    if (e < NETOT) atomicAdd(&g_cnt[dst[e]], 1);
}

__global__ void k_scan_a() {
    __shared__ int s[1024];
    int tid = threadIdx.x;
    int i = blockIdx.x * 1024 + tid;
    int v = (i < NNODES) ? g_cnt[i] : 0;
    s[tid] = v;
    __syncthreads();
    #pragma unroll
    for (int o = 1; o < 1024; o <<= 1) {
        int t = (tid >= o) ? s[tid - o] : 0;
        __syncthreads();
        s[tid] += t;
        __syncthreads();
    }
    if (i < NNODES) g_off[i] = s[tid] - v;
    if (tid == 1023) g_bsum[blockIdx.x] = s[1023];
}

__global__ void k_scan_b() {
    __shared__ int s[128];
    int tid = threadIdx.x;
    int v = (tid < NBLK) ? g_bsum[tid] : 0;
    s[tid] = v;
    __syncthreads();
    #pragma unroll
    for (int o = 1; o < 128; o <<= 1) {
        int t = (tid >= o) ? s[tid - o] : 0;
        __syncthreads();
        s[tid] += t;
        __syncthreads();
    }
    if (tid < NBLK) g_bsum[tid] = s[tid] - v;
}

__global__ void k_scan_c() {
    int i = blockIdx.x * blockDim.x + threadIdx.x;
    if (i < NNODES) {
        int o = g_off[i] + g_bsum[i >> 10];
        g_off[i] = o;
        g_pos[i] = o;
    }
    if (i == 0) g_off[NNODES] = NETOT;
}

__global__ void k_scatter(const int* __restrict__ src, const int* __restrict__ dst) {
    int e = blockIdx.x * blockDim.x + threadIdx.x;
    if (e >= NETOT) return;
    int r = (e >= 2 * EEDGES) ? 2 : (e >= EEDGES ? 1 : 0);
    int pos = atomicAdd(&g_pos[dst[e]], 1);
    g_eid[pos] = (r << 19) | src[e];
}

// ---------------- pipelined tensor-core GEMM (fp16, 2-pass, K64) ----------
#define GBM 128
#define GBN 128
#define GBK 64
#define NSTEP (INFEAT / GBK)           // 4
#define ROWELEM 72                     // 64 + 8 pad halfs -> 144 B rows
#define TILEB (128 * ROWELEM * 2)      // 18432 B
#define STAGEB (3 * TILEB)             // Ah, Bh, Bl = 55296 B
#define SMEMB (2 * STAGEB)             // 110592 B

__global__ void __launch_bounds__(256, 2)
k_gemm(const float* __restrict__ attn_l, const float* __restrict__ attn_r) {
    extern __shared__ char smem[];
    const uint32_t sb = smem_u32(smem);
    const int tid  = threadIdx.x;
    const int wid  = tid >> 5;
    const int lane = tid & 31;
    const int g    = lane >> 2;
    const int t    = lane & 3;
    const int bm   = blockIdx.x * GBM;
    const int bn   = blockIdx.y * GBN;
    const int r    = blockIdx.z;

    const int mband = (wid & 1) * 64;
    const int nband = (wid >> 1) * 32;

    const int arow_lane = ((lane >> 3) & 1) * 8 + (lane & 7);
    const int ak_lane   = (lane >> 4) * 8;
    const int bn_lane   = (lane >> 4) * 8 + (lane & 7);
    const int bk_lane   = ((lane >> 3) & 1) * 8;

    float acc[4][4][4];
    #pragma unroll
    for (int mi = 0; mi < 4; mi++)
        #pragma unroll
        for (int ni = 0; ni < 4; ni++)
            #pragma unroll
            for (int q = 0; q < 4; q++) acc[mi][ni][q] = 0.f;

    // 3 matrices x 128 rows x 8 segs = 3072 chunks / 256 threads = 12 each
    auto load_stage = [&](int buf, int k0) {
        #pragma unroll
        for (int q = 0; q < 12; q++) {
            const int c   = tid + q * 256;
            const int mat = c >> 10;           // 0:Ah 1:Bh 2:Bl
            const int row = (c >> 3) & 127;
            const int seg = c & 7;
            const uint32_t dst = sb + buf * STAGEB + mat * TILEB + row * 144 + seg * 16;
            const __half* src;
            int size = 16;
            if (mat == 0) {
                int gr = bm + row;
                if (gr >= NNODES) { gr = 0; size = 0; }
                src = g_xh + (long)gr * INFEAT + k0 + seg * 8;
            } else {
                src = (mat == 1 ? g_wth : g_wtl) + ((long)r * HF + bn + row) * INFEAT + k0 + seg * 8;
            }
            cp16(dst, src, size);
        }
    };

    load_stage(0, 0);
    CP_COMMIT();

    for (int step = 0; step < NSTEP; step++) {
        const int buf = step & 1;
        if (step + 1 < NSTEP) {
            load_stage(buf ^ 1, (step + 1) * GBK);
            CP_COMMIT();
            CP_WAIT(1);
        } else {
            CP_WAIT(0);
        }
        __syncthreads();

        const uint32_t baseA  = sb + buf * STAGEB;
        const uint32_t baseBh = baseA + TILEB;
        const uint32_t baseBl = baseA + 2 * TILEB;

        #pragma unroll
        for (int kf = 0; kf < 4; kf++) {
            const int kk = kf * 16;
            uint32_t bh[4][2], bl[4][2];
            #pragma unroll
            for (int np = 0; np < 2; np++) {
                const uint32_t off =
                    ((nband + np * 16 + bn_lane) * ROWELEM + kk + bk_lane) * 2;
                LDMX4(bh[np * 2][0], bh[np * 2][1], bh[np * 2 + 1][0], bh[np * 2 + 1][1],
                      baseBh + off);
                LDMX4(bl[np * 2][0], bl[np * 2][1], bl[np * 2 + 1][0], bl[np * 2 + 1][1],
                      baseBl + off);
            }
            #pragma unroll
            for (int mi = 0; mi < 4; mi++) {
                const uint32_t offA =
                    ((mband + mi * 16 + arow_lane) * ROWELEM + kk + ak_lane) * 2;
                uint32_t ah[4];
                LDMX4(ah[0], ah[1], ah[2], ah[3], baseA + offA);
                #pragma unroll
                for (int ni = 0; ni < 4; ni++) {
                    mma_f16(acc[mi][ni], ah, bh[ni]);
                    mma_f16(acc[mi][ni], ah, bl[ni]);
                }
            }
        }
        __syncthreads();
    }

    const int head = (bn + nband) >> 6;
    float alc[4][2], arc[4][2];
    #pragma unroll
    for (int ni = 0; ni < 4; ni++)
        #pragma unroll
        for (int j = 0; j < 2; j++) {
            const int col = bn + nband + ni * 8 + t * 2 + j;
            alc[ni][j] = attn_l[r * HF + col];
            arc[ni][j] = attn_r[r * HF + col];
        }

    #pragma unroll
    for (int mi = 0; mi < 4; mi++) {
        #pragma unroll
        for (int rh = 0; rh < 2; rh++) {
            const int row = mband + mi * 16 + g + rh * 8;
            const int gr  = bm + row;
            const bool ok = (gr < NNODES);
            float sl = 0.f, sr = 0.f;
            #pragma unroll
            for (int ni = 0; ni < 4; ni++) {
                const float z0 = acc[mi][ni][rh * 2 + 0];
                const float z1 = acc[mi][ni][rh * 2 + 1];
                sl = fmaf(z0, alc[ni][0], sl); sl = fmaf(z1, alc[ni][1], sl);
                sr = fmaf(z0, arc[ni][0], sr); sr = fmaf(z1, arc[ni][1], sr);
                if (ok) {
                    const int col = bn + nband + ni * 8 + t * 2;
                    __half2 zz = __floats2half2_rn(z0, z1);
                    *(__half2*)&g_z[((long)r * NNODES + gr) * HF + col] = zz;
                }
            }
            sl += __shfl_xor_sync(0xffffffffu, sl, 1);
            sl += __shfl_xor_sync(0xffffffffu, sl, 2);
            sr += __shfl_xor_sync(0xffffffffu, sr, 1);
            sr += __shfl_xor_sync(0xffffffffu, sr, 2);
            if (ok && t == 0) {
                atomicAdd(&g_el[((long)r * NNODES + gr) * HHEADS + head], sl);
                atomicAdd(&g_er[((long)r * NNODES + gr) * HHEADS + head], sr);
            }
        }
    }
}

// ---------------- single-pass pull aggregation + bias + ELU ----------------
__global__ void __launch_bounds__(64)
k_agg(const float* __restrict__ bias, float* __restrict__ out) {
    int d = blockIdx.x;
    int g = threadIdx.x;                    // columns [g*4, g*4+4)
    int h = g >> 4;

    int off0 = g_off[d];
    int off1 = g_off[d + 1];

    float er0 = g_er[((long)0 * NNODES + d) * HHEADS + h];
    float er1 = g_er[((long)1 * NNODES + d) * HHEADS + h];
    float er2 = g_er[((long)2 * NNODES + d) * HHEADS + h];

    float n0x = 0.f, n0y = 0.f, n0z = 0.f, n0w = 0.f, den0 = 0.f;
    float n1x = 0.f, n1y = 0.f, n1z = 0.f, n1w = 0.f, den1 = 0.f;
    float n2x = 0.f, n2y = 0.f, n2z = 0.f, n2w = 0.f, den2 = 0.f;

    #pragma unroll 4
    for (int i = off0; i < off1; i++) {
        int p = __ldg(&g_eid[i]);
        int r = p >> 19;
        int s = p & 0x7FFFF;
        long idx = (long)r * NNODES + s;
        float erv = (r == 0) ? er0 : (r == 1) ? er1 : er2;
        float v = __ldg(&g_el[idx * HHEADS + h]) + erv;
        v = (v > 0.f) ? v : NEG_SLOPE * v;
        float ev = expf(v);
        uint2 zr = *(const uint2*)&g_z[idx * HF + g * 4];
        float2 f0 = __half22float2(*(const __half2*)&zr.x);
        float2 f1 = __half22float2(*(const __half2*)&zr.y);
        if (r == 0) {
            den0 += ev;
            n0x = fmaf(ev, f0.x, n0x); n0y = fmaf(ev, f0.y, n0y);
            n0z = fmaf(ev, f1.x, n0z); n0w = fmaf(ev, f1.y, n0w);
        } else if (r == 1) {
            den1 += ev;
            n1x = fmaf(ev, f0.x, n1x); n1y = fmaf(ev, f0.y, n1y);
            n1z = fmaf(ev, f1.x, n1z); n1w = fmaf(ev, f1.y, n1w);
        } else {
            den2 += ev;
            n2x = fmaf(ev, f0.x, n2x); n2y = fmaf(ev, f0.y, n2y);
            n2z = fmaf(ev, f1.x, n2z); n2w = fmaf(ev, f1.y, n2w);
        }
    }

    float i0 = (den0 != 0.f) ? 1.0f / den0 : 0.f;
    float i1 = (den1 != 0.f) ? 1.0f / den1 : 0.f;
    float i2 = (den2 != 0.f) ? 1.0f / den2 : 0.f;

    float a0 = n0x * i0 + n1x * i1 + n2x * i2;
    float a1 = n0y * i0 + n1y * i1 + n2y * i2;
    float a2 = n0z * i0 + n1z * i1 + n2z * i2;
    float a3 = n0w * i0 + n1w * i1 + n2w * i2;

    int c = g * 4;
    float b0 = bias[c + 0] + bias[HF + c + 0] + bias[2 * HF + c + 0];
    float b1 = bias[c + 1] + bias[HF + c + 1] + bias[2 * HF + c + 1];
    float b2 = bias[c + 2] + bias[HF + c + 2] + bias[2 * HF + c + 2];
    float b3 = bias[c + 3] + bias[HF + c + 3] + bias[2 * HF + c + 3];
    float v0 = a0 + b0, v1 = a1 + b1, v2 = a2 + b2, v3 = a3 + b3;
    v0 = (v0 > 0.f) ? v0 : expm1f(v0);
    v1 = (v1 > 0.f) ? v1 : expm1f(v1);
    v2 = (v2 > 0.f) ? v2 : expm1f(v2);
    v3 = (v3 > 0.f) ? v3 : expm1f(v3);
    *(float4*)&out[(long)d * HF + c] = make_float4(v0, v1, v2, v3);
}

// ---------------- launch (CSR build overlapped on a second stream) ---------
static cudaStream_t g_s1 = 0;
static cudaEvent_t g_evFork = 0, g_evJoin = 0;

extern "C" void kernel_launch(void* const* d_in, const int* in_sizes, int n_in,
                              void* d_out, int out_size) {
    const float* x      = (const float*)d_in[0];
    const float* W      = (const float*)d_in[1];
    const float* attn_l = (const float*)d_in[2];
    const float* attn_r = (const float*)d_in[3];
    const float* bias   = (const float*)d_in[4];
    const int*   src    = (const int*)d_in[5];
    const int*   dst    = (const int*)d_in[6];
    float* out = (float*)d_out;

    if (g_s1 == 0) {
        cudaStreamCreateWithFlags(&g_s1, cudaStreamNonBlocking);
        cudaEventCreateWithFlags(&g_evFork, cudaEventDisableTiming);
        cudaEventCreateWithFlags(&g_evJoin, cudaEventDisableTiming);
        cudaFuncSetAttribute(k_gemm, cudaFuncAttributeMaxDynamicSharedMemorySize, SMEMB);
    }

    // fork: CSR build on side stream
    cudaEventRecord(g_evFork, 0);
    cudaStreamWaitEvent(g_s1, g_evFork, 0);
    k_zero_cnt<<<(NNODES + 255) / 256, 256, 0, g_s1>>>();
    k_hist<<<(NETOT + 255) / 256, 256, 0, g_s1>>>(dst);
    k_scan_a<<<NBLK, 1024, 0, g_s1>>>();
    k_scan_b<<<1, 128, 0, g_s1>>>();
    k_scan_c<<<(NNODES + 255) / 256, 256, 0, g_s1>>>();
    k_scatter<<<(NETOT + 255) / 256, 256, 0, g_s1>>>(src, dst);
    cudaEventRecord(g_evJoin, g_s1);

    // main stream: prep + GEMM
    k_prep_x<<<(int)(((long)NNODES * INFEAT / 8 + 255) / 256), 256>>>(x);
    k_prep_w<<<(RREL * INFEAT * HF + 255) / 256, 256>>>(W);

    dim3 gg((NNODES + GBM - 1) / GBM, HF / GBN, RREL);
    k_gemm<<<gg, 256, SMEMB>>>(attn_l, attn_r);

    // join: aggregation needs both CSR and z/el/er
    cudaStreamWaitEvent(0, g_evJoin, 0);
    k_agg<<<NNODES, 64>>>(bias, out);
}